// round 13
// baseline (speedup 1.0000x reference)
#include <cuda_runtime.h>
#include <math.h>

#define B 8
#define N 256
#define D 128
#define H 256
#define BN (B * N)   // 2048

// Scratch (allocation-free rule: device globals), 16B aligned for vector access
__device__ __align__(16) float g_hi[BN * H];   // slots @ W_m1[:D]
__device__ __align__(16) float g_hj[BN * H];   // slots @ W_m1[D:] + b_m1
__device__ __align__(16) float g_G [BN * H];   // sum_j a_ij * gelu(hi_i + hj_j)
__device__ float g_asum[BN];                   // rowsum(adjacency)

// 2*gelu(x) via the tanh formulation + MUFU tanh.approx (sm_75+)
__device__ __forceinline__ float gelu2_tanh(float x) {
    const float xx = x * x;
    const float inner = fmaf(0.0356774081f, xx, 0.7978845608f);
    const float w = x * inner;
    float t; asm("tanh.approx.f32 %0,%1;" : "=f"(t) : "f"(w));
    return fmaf(x, t, x);                                        // x*(1+t)
}

// ---------------------------------------------------------------------------
// Kernel 0: adjacency row sums. Warp per row.
// ---------------------------------------------------------------------------
__global__ __launch_bounds__(256) void asum_kernel(const float* __restrict__ adj)
{
    const int row  = blockIdx.x * 8 + (threadIdx.x >> 5);  // b*N + n
    const int lane = threadIdx.x & 31;
    const float* arow = adj + (size_t)row * N;
    float s = 0.f;
#pragma unroll
    for (int k = 0; k < 8; ++k) s += arow[lane + k * 32];
#pragma unroll
    for (int o = 16; o > 0; o >>= 1) s += __shfl_xor_sync(~0u, s, o);
    if (lane == 0) g_asum[row] = s;
}

// ---------------------------------------------------------------------------
// Kernel 1: proj GEMM, 64x32 tiles (grid 32x16 = 512 blocks), 256 threads.
// ---------------------------------------------------------------------------
#define KC 32
__global__ __launch_bounds__(256) void proj_kernel(
    const float* __restrict__ slots, const float* __restrict__ W_m1,
    const float* __restrict__ b_m1)
{
    const int r0   = blockIdx.x * 64;
    const int part = blockIdx.y >> 3;        // 0 -> hi, 1 -> hj
    const int c0   = (blockIdx.y & 7) * 32;
    const int tid  = threadIdx.x;
    const int ty   = tid >> 4, tx = tid & 15;

    __shared__ float As[64][KC + 1];
    __shared__ float Ws[KC][33];

    float acc[4][2];
#pragma unroll
    for (int r = 0; r < 4; ++r)
#pragma unroll
        for (int c = 0; c < 2; ++c) acc[r][c] = 0.f;

    const float* wsrc = W_m1 + (size_t)(part * D) * H + c0;

    for (int kc = 0; kc < D; kc += KC) {
#pragma unroll
        for (int l = 0; l < 8; ++l) {
            const int idx = tid + l * 256;
            const int r = idx >> 5, k = idx & 31;
            As[r][k] = slots[(r0 + r) * D + kc + k];
        }
#pragma unroll
        for (int l = 0; l < 4; ++l) {
            const int idx = tid + l * 256;
            const int k = idx >> 5, c = idx & 31;
            Ws[k][c] = wsrc[(kc + k) * H + c];
        }
        __syncthreads();

#pragma unroll
        for (int k = 0; k < KC; ++k) {
            float wv[2], av[4];
#pragma unroll
            for (int c = 0; c < 2; ++c) wv[c] = Ws[k][tx + 16 * c];
#pragma unroll
            for (int r = 0; r < 4; ++r) av[r] = As[ty + 16 * r][k];
#pragma unroll
            for (int r = 0; r < 4; ++r)
#pragma unroll
                for (int c = 0; c < 2; ++c)
                    acc[r][c] = fmaf(av[r], wv[c], acc[r][c]);
        }
        __syncthreads();
    }

    if (part == 0) {
#pragma unroll
        for (int r = 0; r < 4; ++r)
#pragma unroll
            for (int c = 0; c < 2; ++c)
                g_hi[(size_t)(r0 + ty + 16 * r) * H + c0 + tx + 16 * c] = acc[r][c];
    } else {
        float bm[2];
#pragma unroll
        for (int c = 0; c < 2; ++c) bm[c] = b_m1[c0 + tx + 16 * c];
#pragma unroll
        for (int r = 0; r < 4; ++r)
#pragma unroll
            for (int c = 0; c < 2; ++c)
                g_hj[(size_t)(r0 + ty + 16 * r) * H + c0 + tx + 16 * c] = acc[r][c] + bm[c];
    }
}

// ---------------------------------------------------------------------------
// Kernel 2: G[b,i,h] = sum_j a[b,i,j] * gelu(hi[b,i,h] + hjp[b,j,h])
// 2 i-rows per block (grid 1024), 128 threads; thread owns h-pair (2t, 2t+1).
// ---------------------------------------------------------------------------
__global__ __launch_bounds__(128) void msg_agg_kernel(
    const float* __restrict__ adj)
{
    const int row0 = blockIdx.x * 2;
    const int b    = row0 >> 8;
    const int i0   = row0 & (N - 1);
    const int tid  = threadIdx.x;

    __shared__ float a_s[2][N];             // prescaled by 0.5 (gelu2 = 2*gelu)
    const float* adj_b = adj + ((size_t)b * N + i0) * N;
#pragma unroll
    for (int idx = tid; idx < 2 * N; idx += 128)
        ((float*)a_s)[idx] = 0.5f * adj_b[idx];
    __syncthreads();

    const float2* hj2 = (const float2*)(g_hj + (size_t)b * N * H) + tid;
    const float2 hi0 = ((const float2*)(g_hi + (size_t) row0      * H))[tid];
    const float2 hi1 = ((const float2*)(g_hi + (size_t)(row0 + 1) * H))[tid];

    float acc00 = 0.f, acc01 = 0.f, acc10 = 0.f, acc11 = 0.f;

#pragma unroll 4
    for (int j = 0; j < N; ++j) {
        const float2 hj = hj2[(size_t)j * (H / 2)];
        const float a0 = a_s[0][j];
        const float a1 = a_s[1][j];
        acc00 = fmaf(a0, gelu2_tanh(hi0.x + hj.x), acc00);
        acc01 = fmaf(a0, gelu2_tanh(hi0.y + hj.y), acc01);
        acc10 = fmaf(a1, gelu2_tanh(hi1.x + hj.x), acc10);
        acc11 = fmaf(a1, gelu2_tanh(hi1.y + hj.y), acc11);
    }

    float2 o0; o0.x = acc00; o0.y = acc01;
    float2 o1; o1.x = acc10; o1.y = acc11;
    ((float2*)(g_G + (size_t) row0      * H))[tid] = o0;
    ((float2*)(g_G + (size_t)(row0 + 1) * H))[tid] = o1;
}

// ---------------------------------------------------------------------------
// Kernel 3: fused epilogue, R=4 rows, 256 threads, grid 512 — v2:
// ALL weights staged through smem in chunks (coalesced batched LDG -> LDS),
// removing the per-k scattered L2 LDGs that caused long_scoreboard stalls.
//   agg = G @ W_m2 + asum*b_m2
//   u   = [slots|agg] @ W_u1 + b_u1 ; LayerNorm ; tanh-gelu
//   out = slots + u @ W_u2 + b_u2
// ---------------------------------------------------------------------------
__global__ __launch_bounds__(256) void epilogue_kernel(
    const float* __restrict__ slots,
    const float* __restrict__ W_m2, const float* __restrict__ b_m2,
    const float* __restrict__ W_u1, const float* __restrict__ b_u1,
    const float* __restrict__ ln_g, const float* __restrict__ ln_b,
    const float* __restrict__ W_u2, const float* __restrict__ b_u2,
    float* __restrict__ out)
{
    const int r0 = blockIdx.x * 4;          // global row = b*N + n
    const int tid = threadIdx.x;
    const int warp = tid >> 5, lane = tid & 31;
    const int d  = tid & 127;               // column for D-wide phases
    const int rb = (tid >> 7) * 2;          // row pair for D-wide phases

    __shared__ float buf_s[4][H];           // G tile, later reused as u tile
    __shared__ float s_s [4][D];
    __shared__ float agg_s[4][D];
    __shared__ float ws[4096];              // 16KB weight staging
    __shared__ float asum_s[4];
    __shared__ float mu_s[4], rstd_s[4];

    for (int idx = tid; idx < 4 * H; idx += 256)
        ((float*)buf_s)[idx] = g_G[r0 * H + idx];
    for (int idx = tid; idx < 4 * D; idx += 256)
        ((float*)s_s)[idx] = slots[r0 * D + idx];
    if (tid < 4) asum_s[tid] = g_asum[r0 + tid];
    __syncthreads();

    // Phase A: agg = G @ W_m2 + asum*b_m2   (K=256, chunks of 32)
    {
        const float bm2 = b_m2[d];
        float a0 = asum_s[rb] * bm2, a1 = asum_s[rb + 1] * bm2;
        for (int kc = 0; kc < H; kc += 32) {
#pragma unroll
            for (int l = 0; l < 16; ++l) {
                const int idx = tid + l * 256;           // 0..4095
                ws[idx] = W_m2[(size_t)(kc + (idx >> 7)) * D + (idx & 127)];
            }
            __syncthreads();
#pragma unroll
            for (int k = 0; k < 32; ++k) {
                const float w = ws[k * 128 + d];
                a0 = fmaf(buf_s[rb][kc + k], w, a0);
                a1 = fmaf(buf_s[rb + 1][kc + k], w, a1);
            }
            __syncthreads();
        }
        agg_s[rb][d] = a0;
        agg_s[rb + 1][d] = a1;
    }
    __syncthreads();

    // Phase C: u = [slots|agg] @ W_u1 + b_u1   (K=256, chunks of 16)
    {
        const int h = tid;
        float uacc[4];
        const float bu = b_u1[h];
#pragma unroll
        for (int r = 0; r < 4; ++r) uacc[r] = bu;

        for (int kc = 0; kc < 2 * D; kc += 16) {
            const float* Asrc = (kc < D) ? &s_s[0][0] : &agg_s[0][0];
            const int kb = kc & (D - 1);
#pragma unroll
            for (int l = 0; l < 16; ++l) {
                const int idx = tid + l * 256;           // 0..4095
                ws[idx] = W_u1[(size_t)(kc + (idx >> 8)) * H + (idx & 255)];
            }
            __syncthreads();
#pragma unroll
            for (int k = 0; k < 16; ++k) {
                const float w = ws[k * 256 + h];
#pragma unroll
                for (int r = 0; r < 4; ++r)
                    uacc[r] = fmaf(Asrc[r * D + kb + k], w, uacc[r]);
            }
            __syncthreads();
        }
#pragma unroll
        for (int r = 0; r < 4; ++r) buf_s[r][h] = uacc[r];
    }
    __syncthreads();

    // LayerNorm stats: warps 0..3, one row each (two-pass)
    if (warp < 4) {
        const int r = warp;
        float s = 0.f;
#pragma unroll
        for (int k = 0; k < 8; ++k) s += buf_s[r][lane + k * 32];
#pragma unroll
        for (int o = 16; o > 0; o >>= 1) s += __shfl_xor_sync(~0u, s, o);
        const float mu = s * (1.f / H);
        float ss = 0.f;
#pragma unroll
        for (int k = 0; k < 8; ++k) {
            const float v = buf_s[r][lane + k * 32] - mu;
            ss += v * v;
        }
#pragma unroll
        for (int o = 16; o > 0; o >>= 1) ss += __shfl_xor_sync(~0u, ss, o);
        if (lane == 0) {
            mu_s[r]   = mu;
            rstd_s[r] = rsqrtf(ss * (1.f / H) + 1e-5f);
        }
    }
    __syncthreads();

    // normalize + tanh-gelu (in place)
    {
        const int h = tid;
        const float gg = ln_g[h], bb = ln_b[h];
#pragma unroll
        for (int r = 0; r < 4; ++r) {
            const float v = (buf_s[r][h] - mu_s[r]) * rstd_s[r] * gg + bb;
            buf_s[r][h] = 0.5f * gelu2_tanh(v);
        }
    }
    __syncthreads();

    // Phase E: out = slots + u @ W_u2 + b_u2   (K=256, chunks of 32)
    {
        const float bu2 = b_u2[d];
        float o0 = bu2, o1 = bu2;
        for (int kc = 0; kc < H; kc += 32) {
#pragma unroll
            for (int l = 0; l < 16; ++l) {
                const int idx = tid + l * 256;
                ws[idx] = W_u2[(size_t)(kc + (idx >> 7)) * D + (idx & 127)];
            }
            __syncthreads();
#pragma unroll
            for (int k = 0; k < 32; ++k) {
                const float w = ws[k * 128 + d];
                o0 = fmaf(buf_s[rb][kc + k], w, o0);
                o1 = fmaf(buf_s[rb + 1][kc + k], w, o1);
            }
            __syncthreads();
        }
        out[(size_t)(r0 + rb) * D + d]     = s_s[rb][d] + o0;
        out[(size_t)(r0 + rb + 1) * D + d] = s_s[rb + 1][d] + o1;
    }
}

// ---------------------------------------------------------------------------
extern "C" void kernel_launch(void* const* d_in, const int* in_sizes, int n_in,
                              void* d_out, int out_size)
{
    const float* slots = (const float*)d_in[0];
    const float* adj   = (const float*)d_in[1];
    const float* W_m1  = (const float*)d_in[2];
    const float* b_m1  = (const float*)d_in[3];
    const float* W_m2  = (const float*)d_in[4];
    const float* b_m2  = (const float*)d_in[5];
    const float* W_u1  = (const float*)d_in[6];
    const float* b_u1  = (const float*)d_in[7];
    const float* ln_g  = (const float*)d_in[8];
    const float* ln_b  = (const float*)d_in[9];
    const float* W_u2  = (const float*)d_in[10];
    const float* b_u2  = (const float*)d_in[11];
    float* out = (float*)d_out;

    asum_kernel<<<BN / 8, 256>>>(adj);
    dim3 pg(BN / 64, 16);
    proj_kernel<<<pg, 256>>>(slots, W_m1, b_m1);
    msg_agg_kernel<<<BN / 2, 128>>>(adj);
    epilogue_kernel<<<BN / 4, 256>>>(slots, W_m2, b_m2, W_u1, b_u1,
                                     ln_g, ln_b, W_u2, b_u2, out);
}

// round 14
// speedup vs baseline: 1.1347x; 1.1347x over previous
#include <cuda_runtime.h>
#include <math.h>

#define B 8
#define N 256
#define D 128
#define H 256
#define BN (B * N)   // 2048

// Scratch (allocation-free rule: device globals), 16B aligned for vector access
__device__ __align__(16) float g_hi[BN * H];   // slots @ W_m1[:D]
__device__ __align__(16) float g_hj[BN * H];   // slots @ W_m1[D:] + b_m1
__device__ __align__(16) float g_G [BN * H];   // sum_j a_ij * gelu(hi_i + hj_j)
__device__ float g_asum[BN];                   // rowsum(adjacency)

// 2*gelu(x) via the tanh formulation + MUFU tanh.approx (sm_75+)
__device__ __forceinline__ float gelu2_tanh(float x) {
    const float xx = x * x;
    const float inner = fmaf(0.0356774081f, xx, 0.7978845608f);
    const float w = x * inner;
    float t; asm("tanh.approx.f32 %0,%1;" : "=f"(t) : "f"(w));
    return fmaf(x, t, x);                                        // x*(1+t)
}

// ---------------------------------------------------------------------------
// Kernel 0: adjacency row sums. Warp per row.
// ---------------------------------------------------------------------------
__global__ __launch_bounds__(256) void asum_kernel(const float* __restrict__ adj)
{
    const int row  = blockIdx.x * 8 + (threadIdx.x >> 5);  // b*N + n
    const int lane = threadIdx.x & 31;
    const float* arow = adj + (size_t)row * N;
    float s = 0.f;
#pragma unroll
    for (int k = 0; k < 8; ++k) s += arow[lane + k * 32];
#pragma unroll
    for (int o = 16; o > 0; o >>= 1) s += __shfl_xor_sync(~0u, s, o);
    if (lane == 0) g_asum[row] = s;
}

// ---------------------------------------------------------------------------
// Kernel 1: proj GEMM, 64x32 tiles (grid 32x16 = 512 blocks), 256 threads.
// ---------------------------------------------------------------------------
#define KC 32
__global__ __launch_bounds__(256) void proj_kernel(
    const float* __restrict__ slots, const float* __restrict__ W_m1,
    const float* __restrict__ b_m1)
{
    const int r0   = blockIdx.x * 64;
    const int part = blockIdx.y >> 3;        // 0 -> hi, 1 -> hj
    const int c0   = (blockIdx.y & 7) * 32;
    const int tid  = threadIdx.x;
    const int ty   = tid >> 4, tx = tid & 15;

    __shared__ float As[64][KC + 1];
    __shared__ float Ws[KC][33];

    float acc[4][2];
#pragma unroll
    for (int r = 0; r < 4; ++r)
#pragma unroll
        for (int c = 0; c < 2; ++c) acc[r][c] = 0.f;

    const float* wsrc = W_m1 + (size_t)(part * D) * H + c0;

    for (int kc = 0; kc < D; kc += KC) {
#pragma unroll
        for (int l = 0; l < 8; ++l) {
            const int idx = tid + l * 256;
            const int r = idx >> 5, k = idx & 31;
            As[r][k] = slots[(r0 + r) * D + kc + k];
        }
#pragma unroll
        for (int l = 0; l < 4; ++l) {
            const int idx = tid + l * 256;
            const int k = idx >> 5, c = idx & 31;
            Ws[k][c] = wsrc[(kc + k) * H + c];
        }
        __syncthreads();

#pragma unroll
        for (int k = 0; k < KC; ++k) {
            float wv[2], av[4];
#pragma unroll
            for (int c = 0; c < 2; ++c) wv[c] = Ws[k][tx + 16 * c];
#pragma unroll
            for (int r = 0; r < 4; ++r) av[r] = As[ty + 16 * r][k];
#pragma unroll
            for (int r = 0; r < 4; ++r)
#pragma unroll
                for (int c = 0; c < 2; ++c)
                    acc[r][c] = fmaf(av[r], wv[c], acc[r][c]);
        }
        __syncthreads();
    }

    if (part == 0) {
#pragma unroll
        for (int r = 0; r < 4; ++r)
#pragma unroll
            for (int c = 0; c < 2; ++c)
                g_hi[(size_t)(r0 + ty + 16 * r) * H + c0 + tx + 16 * c] = acc[r][c];
    } else {
        float bm[2];
#pragma unroll
        for (int c = 0; c < 2; ++c) bm[c] = b_m1[c0 + tx + 16 * c];
#pragma unroll
        for (int r = 0; r < 4; ++r)
#pragma unroll
            for (int c = 0; c < 2; ++c)
                g_hj[(size_t)(r0 + ty + 16 * r) * H + c0 + tx + 16 * c] = acc[r][c] + bm[c];
    }
}

// ---------------------------------------------------------------------------
// Kernel 2: G[b,i,h] = sum_j a[b,i,j] * gelu(hi[b,i,h] + hjp[b,j,h])
// 2 i-rows per block (grid 1024), 128 threads; thread owns h-pair (2t, 2t+1).
// ---------------------------------------------------------------------------
__global__ __launch_bounds__(128) void msg_agg_kernel(
    const float* __restrict__ adj)
{
    const int row0 = blockIdx.x * 2;
    const int b    = row0 >> 8;
    const int i0   = row0 & (N - 1);
    const int tid  = threadIdx.x;

    __shared__ float a_s[2][N];             // prescaled by 0.5 (gelu2 = 2*gelu)
    const float* adj_b = adj + ((size_t)b * N + i0) * N;
#pragma unroll
    for (int idx = tid; idx < 2 * N; idx += 128)
        ((float*)a_s)[idx] = 0.5f * adj_b[idx];
    __syncthreads();

    const float2* hj2 = (const float2*)(g_hj + (size_t)b * N * H) + tid;
    const float2 hi0 = ((const float2*)(g_hi + (size_t) row0      * H))[tid];
    const float2 hi1 = ((const float2*)(g_hi + (size_t)(row0 + 1) * H))[tid];

    float acc00 = 0.f, acc01 = 0.f, acc10 = 0.f, acc11 = 0.f;

#pragma unroll 4
    for (int j = 0; j < N; ++j) {
        const float2 hj = hj2[(size_t)j * (H / 2)];
        const float a0 = a_s[0][j];
        const float a1 = a_s[1][j];
        acc00 = fmaf(a0, gelu2_tanh(hi0.x + hj.x), acc00);
        acc01 = fmaf(a0, gelu2_tanh(hi0.y + hj.y), acc01);
        acc10 = fmaf(a1, gelu2_tanh(hi1.x + hj.x), acc10);
        acc11 = fmaf(a1, gelu2_tanh(hi1.y + hj.y), acc11);
    }

    float2 o0; o0.x = acc00; o0.y = acc01;
    float2 o1; o1.x = acc10; o1.y = acc11;
    ((float2*)(g_G + (size_t) row0      * H))[tid] = o0;
    ((float2*)(g_G + (size_t)(row0 + 1) * H))[tid] = o1;
}

// ---------------------------------------------------------------------------
// Kernel 3: fused epilogue v3 — 16 rows/block (grid 128), 256 threads,
// transposed A-operands (pitch 17) + chunk-staged weights + 2D register
// blocking: 8-16 FMA per ~3 smem wavefronts (was 2 FMA / 3 wavefronts).
//   Phase A: agg = G @ W_m2 + asum*b_m2            (2r x 4c per thread)
//   Phase C: u = [slots|agg] @ W_u1 + b_u1         (4r x 4c per thread)
//   LN + tanh-gelu (warp per 2 rows, on transposed u)
//   Phase E: out = slots + u @ W_u2 + b_u2         (2r x 4c per thread)
// ---------------------------------------------------------------------------
#define P 17
__global__ __launch_bounds__(256) void epilogue_kernel(
    const float* __restrict__ slots,
    const float* __restrict__ W_m2, const float* __restrict__ b_m2,
    const float* __restrict__ W_u1, const float* __restrict__ b_u1,
    const float* __restrict__ ln_g, const float* __restrict__ ln_b,
    const float* __restrict__ W_u2, const float* __restrict__ b_u2,
    float* __restrict__ out)
{
    const int r0  = blockIdx.x * 16;        // global row = b*N + n
    const int tid = threadIdx.x;
    const int warp = tid >> 5, lane = tid & 31;
    const int cg  = tid & 31;               // phases A/E: cols 4cg..4cg+3
    const int rg  = tid >> 5;               //             rows 2rg, 2rg+1
    const int hg  = tid & 63;               // phase C:    cols 4hg..4hg+3
    const int rg2 = tid >> 6;               //             rows 4rg2..4rg2+3

    __shared__ __align__(16) float bufA[256 * P]; // Gt -> [slots_t|agg_t] -> W_u2 stage
    __shared__ __align__(16) float bufU[256 * P]; // W_m2/W_u1 stage -> u_t
    __shared__ float asum_s[16];

    // Load G transposed: bufA[k][row], coalesced LDG, stride-17 STS (no conflicts)
#pragma unroll
    for (int l = 0; l < 16; ++l) {
        const int idx = tid + l * 256;
        const int row = idx >> 8, k = idx & 255;
        bufA[k * P + row] = g_G[(size_t)(r0 + row) * H + k];
    }
    if (tid < 16) asum_s[tid] = g_asum[r0 + tid];
    __syncthreads();

    // ---- Phase A: agg (K=256, 8 chunks of 32) ----
    float accA[2][4];
    {
        float bm[4];
#pragma unroll
        for (int c = 0; c < 4; ++c) bm[c] = b_m2[4 * cg + c];
#pragma unroll
        for (int r = 0; r < 2; ++r)
#pragma unroll
            for (int c = 0; c < 4; ++c) accA[r][c] = asum_s[2 * rg + r] * bm[c];

        for (int kc = 0; kc < 256; kc += 32) {
#pragma unroll
            for (int l = 0; l < 16; ++l) {
                const int idx = tid + l * 256;
                bufU[idx] = W_m2[(size_t)(kc + (idx >> 7)) * D + (idx & 127)];
            }
            __syncthreads();
#pragma unroll 8
            for (int k = 0; k < 32; ++k) {
                const float4 wv = *(const float4*)&bufU[k * 128 + 4 * cg];
                const float a0 = bufA[(kc + k) * P + 2 * rg];
                const float a1 = bufA[(kc + k) * P + 2 * rg + 1];
                accA[0][0] = fmaf(a0, wv.x, accA[0][0]);
                accA[0][1] = fmaf(a0, wv.y, accA[0][1]);
                accA[0][2] = fmaf(a0, wv.z, accA[0][2]);
                accA[0][3] = fmaf(a0, wv.w, accA[0][3]);
                accA[1][0] = fmaf(a1, wv.x, accA[1][0]);
                accA[1][1] = fmaf(a1, wv.y, accA[1][1]);
                accA[1][2] = fmaf(a1, wv.z, accA[1][2]);
                accA[1][3] = fmaf(a1, wv.w, accA[1][3]);
            }
            __syncthreads();
        }
    }

    // Repack bufA: [0..127] = slots_t, [128..255] = agg_t
#pragma unroll
    for (int r = 0; r < 2; ++r)
#pragma unroll
        for (int c = 0; c < 4; ++c)
            bufA[(128 + 4 * cg + c) * P + 2 * rg + r] = accA[r][c];
#pragma unroll
    for (int l = 0; l < 8; ++l) {
        const int idx = tid + l * 256;
        const int row = idx >> 7, d = idx & 127;
        bufA[d * P + row] = slots[(size_t)(r0 + row) * D + d];
    }
    __syncthreads();

    // ---- Phase C: u = [slots|agg] @ W_u1 + b_u1 (K=256, 16 chunks of 16) ----
    float accU[4][4];
    {
#pragma unroll
        for (int c = 0; c < 4; ++c) {
            const float bu = b_u1[4 * hg + c];
#pragma unroll
            for (int r = 0; r < 4; ++r) accU[r][c] = bu;
        }
        for (int kc = 0; kc < 256; kc += 16) {
#pragma unroll
            for (int l = 0; l < 16; ++l) {
                const int idx = tid + l * 256;
                bufU[idx] = W_u1[(size_t)(kc + (idx >> 8)) * H + (idx & 255)];
            }
            __syncthreads();
#pragma unroll 4
            for (int k = 0; k < 16; ++k) {
                const float4 wv = *(const float4*)&bufU[k * 256 + 4 * hg];
                float a[4];
#pragma unroll
                for (int r = 0; r < 4; ++r) a[r] = bufA[(kc + k) * P + 4 * rg2 + r];
#pragma unroll
                for (int r = 0; r < 4; ++r) {
                    accU[r][0] = fmaf(a[r], wv.x, accU[r][0]);
                    accU[r][1] = fmaf(a[r], wv.y, accU[r][1]);
                    accU[r][2] = fmaf(a[r], wv.z, accU[r][2]);
                    accU[r][3] = fmaf(a[r], wv.w, accU[r][3]);
                }
            }
            __syncthreads();
        }
    }
    // store u transposed into bufU: u_t[h][row]
#pragma unroll
    for (int r = 0; r < 4; ++r)
#pragma unroll
        for (int c = 0; c < 4; ++c)
            bufU[(4 * hg + c) * P + 4 * rg2 + r] = accU[r][c];
    __syncthreads();

    // ---- LayerNorm + tanh-gelu: warp w handles rows 2w, 2w+1 ----
#pragma unroll
    for (int rr = 0; rr < 2; ++rr) {
        const int row = 2 * warp + rr;
        float v[8];
#pragma unroll
        for (int m = 0; m < 8; ++m) v[m] = bufU[(lane + 32 * m) * P + row];
        float s = 0.f;
#pragma unroll
        for (int m = 0; m < 8; ++m) s += v[m];
#pragma unroll
        for (int o = 16; o > 0; o >>= 1) s += __shfl_xor_sync(~0u, s, o);
        const float mu = s * (1.f / H);
        float ss = 0.f;
#pragma unroll
        for (int m = 0; m < 8; ++m) { const float dd = v[m] - mu; ss += dd * dd; }
#pragma unroll
        for (int o = 16; o > 0; o >>= 1) ss += __shfl_xor_sync(~0u, ss, o);
        const float rstd = rsqrtf(ss * (1.f / H) + 1e-5f);
#pragma unroll
        for (int m = 0; m < 8; ++m) {
            const int h = lane + 32 * m;
            const float x = (v[m] - mu) * rstd * ln_g[h] + ln_b[h];
            bufU[h * P + row] = 0.5f * gelu2_tanh(x);
        }
    }
    __syncthreads();

    // ---- Phase E: out = slots + u @ W_u2 + b_u2 (K=256, 8 chunks of 32) ----
    float accO[2][4];
    {
#pragma unroll
        for (int c = 0; c < 4; ++c) {
            const float bu2 = b_u2[4 * cg + c];
            accO[0][c] = bu2; accO[1][c] = bu2;
        }
        for (int kc = 0; kc < 256; kc += 32) {
#pragma unroll
            for (int l = 0; l < 16; ++l) {
                const int idx = tid + l * 256;
                bufA[idx] = W_u2[(size_t)(kc + (idx >> 7)) * D + (idx & 127)];
            }
            __syncthreads();
#pragma unroll 8
            for (int k = 0; k < 32; ++k) {
                const float4 wv = *(const float4*)&bufA[k * 128 + 4 * cg];
                const float a0 = bufU[(kc + k) * P + 2 * rg];
                const float a1 = bufU[(kc + k) * P + 2 * rg + 1];
                accO[0][0] = fmaf(a0, wv.x, accO[0][0]);
                accO[0][1] = fmaf(a0, wv.y, accO[0][1]);
                accO[0][2] = fmaf(a0, wv.z, accO[0][2]);
                accO[0][3] = fmaf(a0, wv.w, accO[0][3]);
                accO[1][0] = fmaf(a1, wv.x, accO[1][0]);
                accO[1][1] = fmaf(a1, wv.y, accO[1][1]);
                accO[1][2] = fmaf(a1, wv.z, accO[1][2]);
                accO[1][3] = fmaf(a1, wv.w, accO[1][3]);
            }
            __syncthreads();
        }
    }
#pragma unroll
    for (int r = 0; r < 2; ++r) {
        const size_t o = (size_t)(r0 + 2 * rg + r) * D + 4 * cg;
        const float4 sv = *(const float4*)&slots[o];
        float4 ov;
        ov.x = sv.x + accO[r][0];
        ov.y = sv.y + accO[r][1];
        ov.z = sv.z + accO[r][2];
        ov.w = sv.w + accO[r][3];
        *(float4*)&out[o] = ov;
    }
}

// ---------------------------------------------------------------------------
extern "C" void kernel_launch(void* const* d_in, const int* in_sizes, int n_in,
                              void* d_out, int out_size)
{
    const float* slots = (const float*)d_in[0];
    const float* adj   = (const float*)d_in[1];
    const float* W_m1  = (const float*)d_in[2];
    const float* b_m1  = (const float*)d_in[3];
    const float* W_m2  = (const float*)d_in[4];
    const float* b_m2  = (const float*)d_in[5];
    const float* W_u1  = (const float*)d_in[6];
    const float* b_u1  = (const float*)d_in[7];
    const float* ln_g  = (const float*)d_in[8];
    const float* ln_b  = (const float*)d_in[9];
    const float* W_u2  = (const float*)d_in[10];
    const float* b_u2  = (const float*)d_in[11];
    float* out = (float*)d_out;

    asum_kernel<<<BN / 8, 256>>>(adj);
    dim3 pg(BN / 64, 16);
    proj_kernel<<<pg, 256>>>(slots, W_m1, b_m1);
    msg_agg_kernel<<<BN / 2, 128>>>(adj);
    epilogue_kernel<<<BN / 16, 256>>>(slots, W_m2, b_m2, W_u1, b_u1,
                                      ln_g, ln_b, W_u2, b_u2, out);
}

// round 15
// speedup vs baseline: 1.1770x; 1.0373x over previous
#include <cuda_runtime.h>
#include <math.h>

#define B 8
#define N 256
#define D 128
#define H 256
#define BN (B * N)   // 2048

// Scratch (allocation-free rule: device globals), 16B aligned for vector access
__device__ __align__(16) float g_hi[BN * H];   // slots @ W_m1[:D]
__device__ __align__(16) float g_hj[BN * H];   // slots @ W_m1[D:] + b_m1
__device__ __align__(16) float g_G [BN * H];   // sum_j a_ij * gelu(hi_i + hj_j)
__device__ float g_asum[BN];                   // rowsum(adjacency)

__device__ __forceinline__ float gelu_exact(float x) {
    return 0.5f * x * (1.0f + erff(x * 0.70710678118654752440f));
}

// 2*gelu(x) via the tanh formulation + MUFU tanh.approx (sm_75+)
__device__ __forceinline__ float gelu2_tanh(float x) {
    const float xx = x * x;
    const float inner = fmaf(0.0356774081f, xx, 0.7978845608f);
    const float w = x * inner;
    float t; asm("tanh.approx.f32 %0,%1;" : "=f"(t) : "f"(w));
    return fmaf(x, t, x);                                        // x*(1+t)
}

// ---------------------------------------------------------------------------
// Kernel 0: adjacency row sums. Warp per row.
// ---------------------------------------------------------------------------
__global__ __launch_bounds__(256) void asum_kernel(const float* __restrict__ adj)
{
    const int row  = blockIdx.x * 8 + (threadIdx.x >> 5);  // b*N + n
    const int lane = threadIdx.x & 31;
    const float* arow = adj + (size_t)row * N;
    float s = 0.f;
#pragma unroll
    for (int k = 0; k < 8; ++k) s += arow[lane + k * 32];
#pragma unroll
    for (int o = 16; o > 0; o >>= 1) s += __shfl_xor_sync(~0u, s, o);
    if (lane == 0) g_asum[row] = s;
}

// ---------------------------------------------------------------------------
// Kernel 1: proj GEMM, 64x32 tiles (grid 32x16 = 512 blocks), 256 threads.
// ---------------------------------------------------------------------------
#define KC 32
__global__ __launch_bounds__(256) void proj_kernel(
    const float* __restrict__ slots, const float* __restrict__ W_m1,
    const float* __restrict__ b_m1)
{
    const int r0   = blockIdx.x * 64;
    const int part = blockIdx.y >> 3;        // 0 -> hi, 1 -> hj
    const int c0   = (blockIdx.y & 7) * 32;
    const int tid  = threadIdx.x;
    const int ty   = tid >> 4, tx = tid & 15;

    __shared__ float As[64][KC + 1];
    __shared__ float Ws[KC][33];

    float acc[4][2];
#pragma unroll
    for (int r = 0; r < 4; ++r)
#pragma unroll
        for (int c = 0; c < 2; ++c) acc[r][c] = 0.f;

    const float* wsrc = W_m1 + (size_t)(part * D) * H + c0;

    for (int kc = 0; kc < D; kc += KC) {
#pragma unroll
        for (int l = 0; l < 8; ++l) {
            const int idx = tid + l * 256;
            const int r = idx >> 5, k = idx & 31;
            As[r][k] = slots[(r0 + r) * D + kc + k];
        }
#pragma unroll
        for (int l = 0; l < 4; ++l) {
            const int idx = tid + l * 256;
            const int k = idx >> 5, c = idx & 31;
            Ws[k][c] = wsrc[(kc + k) * H + c];
        }
        __syncthreads();

#pragma unroll
        for (int k = 0; k < KC; ++k) {
            float wv[2], av[4];
#pragma unroll
            for (int c = 0; c < 2; ++c) wv[c] = Ws[k][tx + 16 * c];
#pragma unroll
            for (int r = 0; r < 4; ++r) av[r] = As[ty + 16 * r][k];
#pragma unroll
            for (int r = 0; r < 4; ++r)
#pragma unroll
                for (int c = 0; c < 2; ++c)
                    acc[r][c] = fmaf(av[r], wv[c], acc[r][c]);
        }
        __syncthreads();
    }

    if (part == 0) {
#pragma unroll
        for (int r = 0; r < 4; ++r)
#pragma unroll
            for (int c = 0; c < 2; ++c)
                g_hi[(size_t)(r0 + ty + 16 * r) * H + c0 + tx + 16 * c] = acc[r][c];
    } else {
        float bm[2];
#pragma unroll
        for (int c = 0; c < 2; ++c) bm[c] = b_m1[c0 + tx + 16 * c];
#pragma unroll
        for (int r = 0; r < 4; ++r)
#pragma unroll
            for (int c = 0; c < 2; ++c)
                g_hj[(size_t)(r0 + ty + 16 * r) * H + c0 + tx + 16 * c] = acc[r][c] + bm[c];
    }
}

// ---------------------------------------------------------------------------
// Kernel 2: G[b,i,h] = sum_j a[b,i,j] * gelu(hi[b,i,h] + hjp[b,j,h])
// 2 i-rows per block (grid 1024), 128 threads; thread owns h-pair (2t, 2t+1).
// ---------------------------------------------------------------------------
__global__ __launch_bounds__(128) void msg_agg_kernel(
    const float* __restrict__ adj)
{
    const int row0 = blockIdx.x * 2;
    const int b    = row0 >> 8;
    const int i0   = row0 & (N - 1);
    const int tid  = threadIdx.x;

    __shared__ float a_s[2][N];             // prescaled by 0.5 (gelu2 = 2*gelu)
    const float* adj_b = adj + ((size_t)b * N + i0) * N;
#pragma unroll
    for (int idx = tid; idx < 2 * N; idx += 128)
        ((float*)a_s)[idx] = 0.5f * adj_b[idx];
    __syncthreads();

    const float2* hj2 = (const float2*)(g_hj + (size_t)b * N * H) + tid;
    const float2 hi0 = ((const float2*)(g_hi + (size_t) row0      * H))[tid];
    const float2 hi1 = ((const float2*)(g_hi + (size_t)(row0 + 1) * H))[tid];

    float acc00 = 0.f, acc01 = 0.f, acc10 = 0.f, acc11 = 0.f;

#pragma unroll 4
    for (int j = 0; j < N; ++j) {
        const float2 hj = hj2[(size_t)j * (H / 2)];
        const float a0 = a_s[0][j];
        const float a1 = a_s[1][j];
        acc00 = fmaf(a0, gelu2_tanh(hi0.x + hj.x), acc00);
        acc01 = fmaf(a0, gelu2_tanh(hi0.y + hj.y), acc01);
        acc10 = fmaf(a1, gelu2_tanh(hi1.x + hj.x), acc10);
        acc11 = fmaf(a1, gelu2_tanh(hi1.y + hj.y), acc11);
    }

    float2 o0; o0.x = acc00; o0.y = acc01;
    float2 o1; o1.x = acc10; o1.y = acc11;
    ((float2*)(g_G + (size_t) row0      * H))[tid] = o0;
    ((float2*)(g_G + (size_t)(row0 + 1) * H))[tid] = o1;
}

// ---------------------------------------------------------------------------
// Kernel 3: fused epilogue (R11 shape: R=4, 256 threads, grid 512) with
// EXPLICIT register double-buffered weight prefetch in all GEMM loops —
// load-use distance forced to >=16 FMA issues to hide LDG latency.
//   agg = G @ W_m2 + asum*b_m2
//   u   = [slots|agg] @ W_u1 + b_u1 ; LayerNorm ; gelu
//   out = slots + u @ W_u2 + b_u2
// ---------------------------------------------------------------------------
__global__ __launch_bounds__(256) void epilogue_kernel(
    const float* __restrict__ slots,
    const float* __restrict__ W_m2, const float* __restrict__ b_m2,
    const float* __restrict__ W_u1, const float* __restrict__ b_u1,
    const float* __restrict__ ln_g, const float* __restrict__ ln_b,
    const float* __restrict__ W_u2, const float* __restrict__ b_u2,
    float* __restrict__ out)
{
    const int r0 = blockIdx.x * 4;          // global row = b*N + n
    const int tid = threadIdx.x;
    const int warp = tid >> 5, lane = tid & 31;
    const int d  = tid & 127;
    const int rb = (tid >> 7) * 2;

    __shared__ float buf_s[4][H];           // G tile, later reused as u tile
    __shared__ float s_s [4][D];
    __shared__ float agg_s[4][D];
    __shared__ float asum_s[4];
    __shared__ float mu_s[4], rstd_s[4];

    for (int idx = tid; idx < 4 * H; idx += 256)
        ((float*)buf_s)[idx] = g_G[r0 * H + idx];
    for (int idx = tid; idx < 4 * D; idx += 256)
        ((float*)s_s)[idx] = slots[r0 * D + idx];
    if (tid < 4) asum_s[tid] = g_asum[r0 + tid];
    __syncthreads();

    // ---- Phase A: agg = G @ W_m2 + asum*b_m2 (K=256, group-of-8 prefetch)
    {
        const float bm2 = b_m2[d];
        float a0 = asum_s[rb] * bm2, a1 = asum_s[rb + 1] * bm2;
        float wn[8];
#pragma unroll
        for (int j = 0; j < 8; ++j) wn[j] = W_m2[(size_t)j * D + d];
        for (int hh = 0; hh < H; hh += 8) {
            float w[8];
#pragma unroll
            for (int j = 0; j < 8; ++j) w[j] = wn[j];
            if (hh + 8 < H) {
#pragma unroll
                for (int j = 0; j < 8; ++j)
                    wn[j] = W_m2[(size_t)(hh + 8 + j) * D + d];
            }
#pragma unroll
            for (int j = 0; j < 8; ++j) {
                a0 = fmaf(buf_s[rb][hh + j],     w[j], a0);
                a1 = fmaf(buf_s[rb + 1][hh + j], w[j], a1);
            }
        }
        __syncthreads();                     // all reads of buf_s-as-G done
        agg_s[rb][d] = a0;
        agg_s[rb + 1][d] = a1;
    }
    __syncthreads();

    // ---- Phase C: u = [slots|agg] @ W_u1 + b_u1 (distance-2 prefetch)
    {
        const int h = tid;
        float acc[4];
        const float bu = b_u1[h];
#pragma unroll
        for (int r = 0; r < 4; ++r) acc[r] = bu;

        float w1a = W_u1[h],                 w2a = W_u1[(size_t)D * H + h];
        float w1b = W_u1[(size_t)1 * H + h], w2b = W_u1[(size_t)(D + 1) * H + h];
        for (int dd = 0; dd < D; ++dd) {
            const float w1 = w1a, w2 = w2a;
            w1a = w1b; w2a = w2b;
            if (dd + 2 < D) {
                w1b = W_u1[(size_t)(dd + 2) * H + h];
                w2b = W_u1[(size_t)(D + dd + 2) * H + h];
            }
#pragma unroll
            for (int r = 0; r < 4; ++r) {
                acc[r] = fmaf(s_s[r][dd], w1, acc[r]);
                acc[r] = fmaf(agg_s[r][dd], w2, acc[r]);
            }
        }
#pragma unroll
        for (int r = 0; r < 4; ++r) buf_s[r][h] = acc[r];
    }
    __syncthreads();

    // ---- LayerNorm stats: warps 0..3, one row each (two-pass)
    if (warp < 4) {
        const int r = warp;
        float s = 0.f;
#pragma unroll
        for (int k = 0; k < 8; ++k) s += buf_s[r][lane + k * 32];
#pragma unroll
        for (int o = 16; o > 0; o >>= 1) s += __shfl_xor_sync(~0u, s, o);
        const float mu = s * (1.f / H);
        float ss = 0.f;
#pragma unroll
        for (int k = 0; k < 8; ++k) {
            const float v = buf_s[r][lane + k * 32] - mu;
            ss += v * v;
        }
#pragma unroll
        for (int o = 16; o > 0; o >>= 1) ss += __shfl_xor_sync(~0u, ss, o);
        if (lane == 0) {
            mu_s[r]   = mu;
            rstd_s[r] = rsqrtf(ss * (1.f / H) + 1e-5f);
        }
    }
    __syncthreads();

    // ---- normalize + exact gelu (in place)
    {
        const int h = tid;
        const float gg = ln_g[h], bb = ln_b[h];
#pragma unroll
        for (int r = 0; r < 4; ++r) {
            const float v = (buf_s[r][h] - mu_s[r]) * rstd_s[r] * gg + bb;
            buf_s[r][h] = gelu_exact(v);
        }
    }
    __syncthreads();

    // ---- Phase E: out = slots + u @ W_u2 + b_u2 (group-of-8 prefetch)
    {
        const float bu2 = b_u2[d];
        float o0 = bu2, o1 = bu2;
        float wn[8];
#pragma unroll
        for (int j = 0; j < 8; ++j) wn[j] = W_u2[(size_t)j * D + d];
        for (int hh = 0; hh < H; hh += 8) {
            float w[8];
#pragma unroll
            for (int j = 0; j < 8; ++j) w[j] = wn[j];
            if (hh + 8 < H) {
#pragma unroll
                for (int j = 0; j < 8; ++j)
                    wn[j] = W_u2[(size_t)(hh + 8 + j) * D + d];
            }
#pragma unroll
            for (int j = 0; j < 8; ++j) {
                o0 = fmaf(buf_s[rb][hh + j],     w[j], o0);
                o1 = fmaf(buf_s[rb + 1][hh + j], w[j], o1);
            }
        }
        out[(size_t)(r0 + rb) * D + d]     = s_s[rb][d] + o0;
        out[(size_t)(r0 + rb + 1) * D + d] = s_s[rb + 1][d] + o1;
    }
}

// ---------------------------------------------------------------------------
extern "C" void kernel_launch(void* const* d_in, const int* in_sizes, int n_in,
                              void* d_out, int out_size)
{
    const float* slots = (const float*)d_in[0];
    const float* adj   = (const float*)d_in[1];
    const float* W_m1  = (const float*)d_in[2];
    const float* b_m1  = (const float*)d_in[3];
    const float* W_m2  = (const float*)d_in[4];
    const float* b_m2  = (const float*)d_in[5];
    const float* W_u1  = (const float*)d_in[6];
    const float* b_u1  = (const float*)d_in[7];
    const float* ln_g  = (const float*)d_in[8];
    const float* ln_b  = (const float*)d_in[9];
    const float* W_u2  = (const float*)d_in[10];
    const float* b_u2  = (const float*)d_in[11];
    float* out = (float*)d_out;

    asum_kernel<<<BN / 8, 256>>>(adj);
    dim3 pg(BN / 64, 16);
    proj_kernel<<<pg, 256>>>(slots, W_m1, b_m1);
    msg_agg_kernel<<<BN / 2, 128>>>(adj);
    epilogue_kernel<<<BN / 4, 256>>>(slots, W_m2, b_m2, W_u1, b_u1,
                                     ln_g, ln_b, W_u2, b_u2, out);
}